// round 10
// baseline (speedup 1.0000x reference)
#include <cuda_runtime.h>

#define NN 50000
#define EE 1600000
#define ET (EE + NN)
#define GG 512
#define NCHUNK ((NN + 255) / 256)

// ---------------- scratch (static device arrays; no cudaMalloc) -------------
__device__ __align__(16) float g_h1[NN * 128];
__device__ __align__(16) float g_as1[NN * 4];
__device__ __align__(16) float g_ad1[NN * 4];
__device__ __align__(16) float g_out1[NN * 128];
__device__ __align__(16) float g_h2[NN * 32];
__device__ __align__(16) float g_as2[NN];
__device__ __align__(16) float g_ad2[NN];
__device__ __align__(16) float g_pool[GG * 32];
__device__ __align__(16) float g_cnt[GG];
__device__ int g_deg[NN];
__device__ int g_rowptr[NN + 1];
__device__ int g_cursor[NN];
__device__ int g_csrc[ET];
__device__ int g_bsum[NCHUNK];

// ---------------- helpers ---------------------------------------------------
__device__ __forceinline__ float lrelu(float x) { return x > 0.f ? x : 0.2f * x; }
__device__ __forceinline__ float eluf(float x)  { return x > 0.f ? x : (__expf(x) - 1.f); }
__device__ __forceinline__ int clampi(int v, int hi) { return v < 0 ? 0 : (v > hi ? hi : v); }

// ---------------- init -------------------------------------------------------
__global__ void k_init() {
    int i = blockIdx.x * blockDim.x + threadIdx.x;
    int st = gridDim.x * blockDim.x;
    for (int j = i; j < NN; j += st) g_deg[j] = 0;
    for (int j = i; j < GG * 32; j += st) g_pool[j] = 0.f;
    for (int j = i; j < GG; j += st) g_cnt[j] = 0.f;
}

// ---------------- CSR build: 4 edges/thread, int4 loads ----------------------
// edge_index arrives as int32 (harness downcasts int64): row0 = src, row1 = dst.
__global__ void k_deg(const int* __restrict__ ei) {
    int i0 = (blockIdx.x * blockDim.x + threadIdx.x) * 4;
    if (i0 >= ET) return;
    if (i0 + 3 < EE) {
        int4 d4 = *(const int4*)&ei[EE + i0];
        atomicAdd(&g_deg[clampi(d4.x, NN - 1)], 1);
        atomicAdd(&g_deg[clampi(d4.y, NN - 1)], 1);
        atomicAdd(&g_deg[clampi(d4.z, NN - 1)], 1);
        atomicAdd(&g_deg[clampi(d4.w, NN - 1)], 1);
    } else {
#pragma unroll
        for (int j = 0; j < 4; j++) {
            int i = i0 + j;
            if (i >= ET) break;
            int d = (i < EE) ? ei[EE + i] : (i - EE);
            atomicAdd(&g_deg[clampi(d, NN - 1)], 1);
        }
    }
}

// block sums of 256-element chunks
__global__ void k_bsum() {
    __shared__ int ws[8];
    int tid = threadIdx.x;
    int idx = blockIdx.x * 256 + tid;
    int v = (idx < NN) ? g_deg[idx] : 0;
#pragma unroll
    for (int off = 16; off; off >>= 1) v += __shfl_xor_sync(0xffffffffu, v, off);
    if ((tid & 31) == 0) ws[tid >> 5] = v;
    __syncthreads();
    if (tid == 0) {
        int s = 0;
#pragma unroll
        for (int w = 0; w < 8; w++) s += ws[w];
        g_bsum[blockIdx.x] = s;
    }
}

// per-chunk scan; each block computes its own prefix over block sums
__global__ void k_chscan() {
    __shared__ int red[8];
    __shared__ int wsum[8];
    __shared__ int pre_s;
    int b = blockIdx.x, tid = threadIdx.x, lane = tid & 31, wid = tid >> 5;

    int pv = (tid < b && tid < NCHUNK) ? g_bsum[tid] : 0;
#pragma unroll
    for (int off = 16; off; off >>= 1) pv += __shfl_xor_sync(0xffffffffu, pv, off);
    if (lane == 0) red[wid] = pv;
    __syncthreads();
    if (tid == 0) {
        int p = 0;
#pragma unroll
        for (int w = 0; w < 8; w++) p += red[w];
        pre_s = p;
    }
    __syncthreads();

    int idx = b * 256 + tid;
    int v = (idx < NN) ? g_deg[idx] : 0;
    int sc = v;
#pragma unroll
    for (int off = 1; off < 32; off <<= 1) {
        int t = __shfl_up_sync(0xffffffffu, sc, off);
        if (lane >= off) sc += t;
    }
    if (lane == 31) wsum[wid] = sc;
    __syncthreads();
    if (tid == 0) {
        int c = pre_s;
#pragma unroll
        for (int w = 0; w < 8; w++) { int t = wsum[w]; wsum[w] = c; c += t; }
    }
    __syncthreads();
    int excl = wsum[wid] + sc - v;
    if (idx < NN) { g_rowptr[idx] = excl; g_cursor[idx] = excl; }
    if (b == gridDim.x - 1 && tid == 255) g_rowptr[NN] = excl + v;
}

__global__ void k_scatter(const int* __restrict__ ei) {
    int i0 = (blockIdx.x * blockDim.x + threadIdx.x) * 4;
    if (i0 >= ET) return;
    if (i0 + 3 < EE) {
        int4 s4 = *(const int4*)&ei[i0];
        int4 d4 = *(const int4*)&ei[EE + i0];
        int sl0 = atomicAdd(&g_cursor[clampi(d4.x, NN - 1)], 1);
        int sl1 = atomicAdd(&g_cursor[clampi(d4.y, NN - 1)], 1);
        int sl2 = atomicAdd(&g_cursor[clampi(d4.z, NN - 1)], 1);
        int sl3 = atomicAdd(&g_cursor[clampi(d4.w, NN - 1)], 1);
        if (sl0 >= 0 && sl0 < ET) g_csrc[sl0] = clampi(s4.x, NN - 1);
        if (sl1 >= 0 && sl1 < ET) g_csrc[sl1] = clampi(s4.y, NN - 1);
        if (sl2 >= 0 && sl2 < ET) g_csrc[sl2] = clampi(s4.z, NN - 1);
        if (sl3 >= 0 && sl3 < ET) g_csrc[sl3] = clampi(s4.w, NN - 1);
    } else {
#pragma unroll
        for (int j = 0; j < 4; j++) {
            int i = i0 + j;
            if (i >= ET) break;
            int s, d;
            if (i < EE) { s = clampi(ei[i], NN - 1); d = clampi(ei[EE + i], NN - 1); }
            else        { s = i - EE; d = s; }
            int slot = atomicAdd(&g_cursor[d], 1);
            if (slot >= 0 && slot < ET) g_csrc[slot] = s;
        }
    }
}

// ---------------- layer1 linear + attention scalars -------------------------
__global__ void k_lin1(const float* __restrict__ x, const float* __restrict__ W,
                       const float* __restrict__ asv, const float* __restrict__ adv) {
    extern __shared__ float sm[];
    float* Ws = sm;              // 128*128
    float* xs = sm + 128 * 128;  // 64*128
    int t = threadIdx.x;
    int base = blockIdx.x * 64;

    for (int i = t; i < 4096; i += 256) ((float4*)Ws)[i] = ((const float4*)W)[i];
    for (int i = t; i < 2048; i += 256) {
        int node = base + (i >> 5);
        ((float4*)xs)[i] = (node < NN) ? ((const float4*)x)[node * 32 + (i & 31)]
                                       : make_float4(0.f, 0.f, 0.f, 0.f);
    }
    __syncthreads();

    int cx = t & 31;
    int ng = t >> 5;
    float acc[8][4];
#pragma unroll
    for (int j = 0; j < 8; j++) { acc[j][0]=acc[j][1]=acc[j][2]=acc[j][3]=0.f; }

    for (int k = 0; k < 128; k++) {
        float4 w4 = ((float4*)Ws)[k * 32 + cx];
#pragma unroll
        for (int j = 0; j < 8; j++) {
            float xv = xs[(ng * 8 + j) * 128 + k];
            acc[j][0] += xv * w4.x; acc[j][1] += xv * w4.y;
            acc[j][2] += xv * w4.z; acc[j][3] += xv * w4.w;
        }
    }

    int c0 = 4 * cx;
    float as0 = asv[c0], as1 = asv[c0+1], as2 = asv[c0+2], as3 = asv[c0+3];
    float ad0 = adv[c0], ad1 = adv[c0+1], ad2 = adv[c0+2], ad3 = adv[c0+3];
    int head = cx >> 3;

#pragma unroll
    for (int j = 0; j < 8; j++) {
        int node = base + ng * 8 + j;
        bool valid = node < NN;
        float4 o = make_float4(acc[j][0], acc[j][1], acc[j][2], acc[j][3]);
        if (valid) *(float4*)&g_h1[node * 128 + c0] = o;
        float sv = o.x*as0 + o.y*as1 + o.z*as2 + o.w*as3;
        float dv = o.x*ad0 + o.y*ad1 + o.z*ad2 + o.w*ad3;
#pragma unroll
        for (int off = 4; off; off >>= 1) {
            sv += __shfl_down_sync(0xffffffffu, sv, off, 8);
            dv += __shfl_down_sync(0xffffffffu, dv, off, 8);
        }
        if (valid && (cx & 7) == 0) {
            g_as1[node * 4 + head] = sv;
            g_ad1[node * 4 + head] = dv;
        }
    }
}

// ---------------- layer1 aggregation: one pass, pipelined, fp32 gather -------
__global__ void k_agg1(const float* __restrict__ bias) {
    int gt = blockIdx.x * blockDim.x + threadIdx.x;
    int d = gt >> 5, lane = gt & 31;
    if (d >= NN) return;
    int e0 = g_rowptr[d], e1 = g_rowptr[d + 1];
    int head = lane >> 3;
    float adh = g_ad1[d * 4 + head];

    float den = 0.f;
    float a0 = 0.f, a1 = 0.f, a2 = 0.f, a3 = 0.f;

    int s_cur = (e0 < e1) ? g_csrc[e0] : 0;
    float as_cur = g_as1[s_cur * 4 + head];
    float4 h_cur = *(const float4*)&g_h1[s_cur * 128 + 4 * lane];

    for (int k = e0; k < e1; k++) {
        int s_nxt = (k + 1 < e1) ? g_csrc[k + 1] : s_cur;      // warp-uniform
        float as_nxt = g_as1[s_nxt * 4 + head];
        float4 h_nxt = *(const float4*)&g_h1[s_nxt * 128 + 4 * lane];

        float ex = __expf(lrelu(as_cur + adh));
        den += ex;
        a0 += ex * h_cur.x; a1 += ex * h_cur.y;
        a2 += ex * h_cur.z; a3 += ex * h_cur.w;

        as_cur = as_nxt; h_cur = h_nxt;
    }
    float inv = 1.f / den;
    int c0 = 4 * lane;
    float4 o;
    o.x = eluf(a0 * inv + bias[c0 + 0]);
    o.y = eluf(a1 * inv + bias[c0 + 1]);
    o.z = eluf(a2 * inv + bias[c0 + 2]);
    o.w = eluf(a3 * inv + bias[c0 + 3]);
    *(float4*)&g_out1[d * 128 + c0] = o;
}

// ---------------- layer2 linear + attention scalars -------------------------
__global__ void k_lin2(const float* __restrict__ W,
                       const float* __restrict__ asv, const float* __restrict__ adv) {
    extern __shared__ float sm[];
    float* Ws = sm;              // 128*32
    float* xs = sm + 128 * 32;   // 128*128
    int t = threadIdx.x;
    int base = blockIdx.x * 128;

    for (int i = t; i < 1024; i += 256) ((float4*)Ws)[i] = ((const float4*)W)[i];
    for (int i = t; i < 4096; i += 256) {
        int node = base + (i >> 5);
        ((float4*)xs)[i] = (node < NN) ? ((const float4*)g_out1)[node * 32 + (i & 31)]
                                       : make_float4(0.f, 0.f, 0.f, 0.f);
    }
    __syncthreads();

    int cx = t & 7;
    int ng = t >> 3;
    float acc[4][4];
#pragma unroll
    for (int j = 0; j < 4; j++) { acc[j][0]=acc[j][1]=acc[j][2]=acc[j][3]=0.f; }

    for (int k = 0; k < 128; k++) {
        float4 w4 = ((float4*)Ws)[k * 8 + cx];
#pragma unroll
        for (int j = 0; j < 4; j++) {
            float xv = xs[(ng * 4 + j) * 128 + k];
            acc[j][0] += xv * w4.x; acc[j][1] += xv * w4.y;
            acc[j][2] += xv * w4.z; acc[j][3] += xv * w4.w;
        }
    }

    int c0 = 4 * cx;
    float as0 = asv[c0], as1 = asv[c0+1], as2 = asv[c0+2], as3 = asv[c0+3];
    float ad0 = adv[c0], ad1 = adv[c0+1], ad2 = adv[c0+2], ad3 = adv[c0+3];

#pragma unroll
    for (int j = 0; j < 4; j++) {
        int node = base + ng * 4 + j;
        bool valid = node < NN;
        float4 o = make_float4(acc[j][0], acc[j][1], acc[j][2], acc[j][3]);
        if (valid) *(float4*)&g_h2[node * 32 + c0] = o;
        float sv = o.x*as0 + o.y*as1 + o.z*as2 + o.w*as3;
        float dv = o.x*ad0 + o.y*ad1 + o.z*ad2 + o.w*ad3;
#pragma unroll
        for (int off = 4; off; off >>= 1) {
            sv += __shfl_down_sync(0xffffffffu, sv, off, 8);
            dv += __shfl_down_sync(0xffffffffu, dv, off, 8);
        }
        if (valid && cx == 0) { g_as2[node] = sv; g_ad2[node] = dv; }
    }
}

// ---------------- layer2 aggregation: one pass + bias/ELU/mean-pool ----------
__global__ void k_agg2(const float* __restrict__ bias, const int* __restrict__ batch) {
    int gt = blockIdx.x * blockDim.x + threadIdx.x;
    int d = gt >> 5, lane = gt & 31;
    if (d >= NN) return;
    int e0 = g_rowptr[d], e1 = g_rowptr[d + 1];
    float ad = g_ad2[d];

    float den = 0.f, acc = 0.f;
    int s_cur = (e0 < e1) ? g_csrc[e0] : 0;
    float as_cur = g_as2[s_cur];
    float h_cur = g_h2[s_cur * 32 + lane];
    for (int k = e0; k < e1; k++) {
        int s_nxt = (k + 1 < e1) ? g_csrc[k + 1] : s_cur;
        float as_nxt = g_as2[s_nxt];
        float h_nxt = g_h2[s_nxt * 32 + lane];
        float ex = __expf(lrelu(as_cur + ad));
        den += ex;
        acc += ex * h_cur;
        as_cur = as_nxt; h_cur = h_nxt;
    }
    float v = eluf(acc / den + bias[lane]);
    int g = clampi(batch[d], GG - 1);
    atomicAdd(&g_pool[g * 32 + lane], v);
    if (lane == 0) atomicAdd(&g_cnt[g], 1.f);
}

// ---------------- classifier --------------------------------------------------
__global__ void k_cls(const float* __restrict__ Wc1, const float* __restrict__ bc1,
                      const float* __restrict__ Wc2, const float* __restrict__ bc2,
                      float* __restrict__ out) {
    int g = blockIdx.x * blockDim.x + threadIdx.x;
    if (g >= GG) return;
    float inv = 1.f / g_cnt[g];
    float p[32];
#pragma unroll
    for (int c = 0; c < 32; c++) p[c] = g_pool[g * 32 + c] * inv;
    float o = bc2[0];
#pragma unroll
    for (int j = 0; j < 16; j++) {
        float z = bc1[j];
#pragma unroll
        for (int c = 0; c < 32; c++) z += p[c] * Wc1[c * 16 + j];
        z = fmaxf(z, 0.f);
        o += z * Wc2[j];
    }
    out[g] = o;
}

// ---------------- launch ------------------------------------------------------
extern "C" void kernel_launch(void* const* d_in, const int* in_sizes, int n_in,
                              void* d_out, int out_size) {
    const float* x     = (const float*)d_in[0];
    const int*   ei    = (const int*)d_in[1];     // int64 -> int32 on device
    const int*   batch = (const int*)d_in[3];     // int64 -> int32
    const float* W1  = (const float*)d_in[4];
    const float* as1 = (const float*)d_in[5];
    const float* ad1 = (const float*)d_in[6];
    const float* b1  = (const float*)d_in[7];
    const float* W2  = (const float*)d_in[8];
    const float* as2 = (const float*)d_in[9];
    const float* ad2 = (const float*)d_in[10];
    const float* b2  = (const float*)d_in[11];
    const float* Wc1 = (const float*)d_in[12];
    const float* bc1 = (const float*)d_in[13];
    const float* Wc2 = (const float*)d_in[14];
    const float* bc2 = (const float*)d_in[15];
    float* out = (float*)d_out;

    cudaFuncSetAttribute(k_lin1, cudaFuncAttributeMaxDynamicSharedMemorySize, 98304);
    cudaFuncSetAttribute(k_lin2, cudaFuncAttributeMaxDynamicSharedMemorySize, 81920);

    k_init<<<256, 256>>>();
    k_deg<<<(ET / 4 + 255) / 256, 256>>>(ei);
    k_bsum<<<NCHUNK, 256>>>();
    k_chscan<<<NCHUNK, 256>>>();
    k_scatter<<<(ET / 4 + 255) / 256, 256>>>(ei);
    k_lin1<<<(NN + 63) / 64, 256, 98304>>>(x, W1, as1, ad1);
    k_agg1<<<(NN * 32 + 255) / 256, 256>>>(b1);
    k_lin2<<<(NN + 127) / 128, 256, 81920>>>(W2, as2, ad2);
    k_agg2<<<(NN * 32 + 255) / 256, 256>>>(b2, batch);
    k_cls<<<2, 256>>>(Wc1, bc1, Wc2, bc2, out);
}

// round 13
// speedup vs baseline: 1.1000x; 1.1000x over previous
#include <cuda_runtime.h>

#define NN 50000
#define EE 1600000
#define ET (EE + NN)
#define GG 512
#define NCHUNK ((NN + 255) / 256)

// ---------------- scratch (static device arrays; no cudaMalloc) -------------
__device__ __align__(16) float g_h1[NN * 128];
__device__ __align__(16) float g_as1[NN * 4];
__device__ __align__(16) float g_ad1[NN * 4];
__device__ __align__(16) float g_out1[NN * 128];
__device__ __align__(16) float g_h2[NN * 32];
__device__ __align__(16) float g_as2[NN];
__device__ __align__(16) float g_ad2[NN];
__device__ __align__(16) float g_pool[GG * 32];
__device__ __align__(16) float g_cnt[GG];
__device__ int g_deg[NN];
__device__ int g_rowptr[NN + 1];
__device__ int g_cursor[NN];
__device__ int g_csrc[ET];
__device__ int g_bsum[NCHUNK];

// ---------------- helpers ---------------------------------------------------
__device__ __forceinline__ float lrelu(float x) { return x > 0.f ? x : 0.2f * x; }
__device__ __forceinline__ float eluf(float x)  { return x > 0.f ? x : (__expf(x) - 1.f); }
__device__ __forceinline__ int clampi(int v, int hi) { return v < 0 ? 0 : (v > hi ? hi : v); }

// ---------------- init -------------------------------------------------------
__global__ void k_init() {
    int i = blockIdx.x * blockDim.x + threadIdx.x;
    int st = gridDim.x * blockDim.x;
    for (int j = i; j < NN; j += st) g_deg[j] = 0;
    for (int j = i; j < GG * 32; j += st) g_pool[j] = 0.f;
    for (int j = i; j < GG; j += st) g_cnt[j] = 0.f;
}

// ---------------- CSR build: 4 edges/thread, int4 loads ----------------------
// edge_index arrives as int32 (harness downcasts int64): row0 = src, row1 = dst.
__global__ void k_deg(const int* __restrict__ ei) {
    int i0 = (blockIdx.x * blockDim.x + threadIdx.x) * 4;
    if (i0 >= ET) return;
    if (i0 + 3 < EE) {
        int4 d4 = *(const int4*)&ei[EE + i0];
        atomicAdd(&g_deg[clampi(d4.x, NN - 1)], 1);
        atomicAdd(&g_deg[clampi(d4.y, NN - 1)], 1);
        atomicAdd(&g_deg[clampi(d4.z, NN - 1)], 1);
        atomicAdd(&g_deg[clampi(d4.w, NN - 1)], 1);
    } else {
#pragma unroll
        for (int j = 0; j < 4; j++) {
            int i = i0 + j;
            if (i >= ET) break;
            int d = (i < EE) ? ei[EE + i] : (i - EE);
            atomicAdd(&g_deg[clampi(d, NN - 1)], 1);
        }
    }
}

// block sums of 256-element chunks
__global__ void k_bsum() {
    __shared__ int ws[8];
    int tid = threadIdx.x;
    int idx = blockIdx.x * 256 + tid;
    int v = (idx < NN) ? g_deg[idx] : 0;
#pragma unroll
    for (int off = 16; off; off >>= 1) v += __shfl_xor_sync(0xffffffffu, v, off);
    if ((tid & 31) == 0) ws[tid >> 5] = v;
    __syncthreads();
    if (tid == 0) {
        int s = 0;
#pragma unroll
        for (int w = 0; w < 8; w++) s += ws[w];
        g_bsum[blockIdx.x] = s;
    }
}

// per-chunk scan; each block computes its own prefix over block sums
__global__ void k_chscan() {
    __shared__ int red[8];
    __shared__ int wsum[8];
    __shared__ int pre_s;
    int b = blockIdx.x, tid = threadIdx.x, lane = tid & 31, wid = tid >> 5;

    int pv = (tid < b && tid < NCHUNK) ? g_bsum[tid] : 0;
#pragma unroll
    for (int off = 16; off; off >>= 1) pv += __shfl_xor_sync(0xffffffffu, pv, off);
    if (lane == 0) red[wid] = pv;
    __syncthreads();
    if (tid == 0) {
        int p = 0;
#pragma unroll
        for (int w = 0; w < 8; w++) p += red[w];
        pre_s = p;
    }
    __syncthreads();

    int idx = b * 256 + tid;
    int v = (idx < NN) ? g_deg[idx] : 0;
    int sc = v;
#pragma unroll
    for (int off = 1; off < 32; off <<= 1) {
        int t = __shfl_up_sync(0xffffffffu, sc, off);
        if (lane >= off) sc += t;
    }
    if (lane == 31) wsum[wid] = sc;
    __syncthreads();
    if (tid == 0) {
        int c = pre_s;
#pragma unroll
        for (int w = 0; w < 8; w++) { int t = wsum[w]; wsum[w] = c; c += t; }
    }
    __syncthreads();
    int excl = wsum[wid] + sc - v;
    if (idx < NN) { g_rowptr[idx] = excl; g_cursor[idx] = excl; }
    if (b == gridDim.x - 1 && tid == 255) g_rowptr[NN] = excl + v;
}

__global__ void k_scatter(const int* __restrict__ ei) {
    int i0 = (blockIdx.x * blockDim.x + threadIdx.x) * 4;
    if (i0 >= ET) return;
    if (i0 + 3 < EE) {
        int4 s4 = *(const int4*)&ei[i0];
        int4 d4 = *(const int4*)&ei[EE + i0];
        int sl0 = atomicAdd(&g_cursor[clampi(d4.x, NN - 1)], 1);
        int sl1 = atomicAdd(&g_cursor[clampi(d4.y, NN - 1)], 1);
        int sl2 = atomicAdd(&g_cursor[clampi(d4.z, NN - 1)], 1);
        int sl3 = atomicAdd(&g_cursor[clampi(d4.w, NN - 1)], 1);
        if (sl0 >= 0 && sl0 < ET) g_csrc[sl0] = clampi(s4.x, NN - 1);
        if (sl1 >= 0 && sl1 < ET) g_csrc[sl1] = clampi(s4.y, NN - 1);
        if (sl2 >= 0 && sl2 < ET) g_csrc[sl2] = clampi(s4.z, NN - 1);
        if (sl3 >= 0 && sl3 < ET) g_csrc[sl3] = clampi(s4.w, NN - 1);
    } else {
#pragma unroll
        for (int j = 0; j < 4; j++) {
            int i = i0 + j;
            if (i >= ET) break;
            int s, d;
            if (i < EE) { s = clampi(ei[i], NN - 1); d = clampi(ei[EE + i], NN - 1); }
            else        { s = i - EE; d = s; }
            int slot = atomicAdd(&g_cursor[d], 1);
            if (slot >= 0 && slot < ET) g_csrc[slot] = s;
        }
    }
}

// ---------------- layer1 linear + attention scalars -------------------------
__global__ void k_lin1(const float* __restrict__ x, const float* __restrict__ W,
                       const float* __restrict__ asv, const float* __restrict__ adv) {
    extern __shared__ float sm[];
    float* Ws = sm;              // 128*128
    float* xs = sm + 128 * 128;  // 64*128
    int t = threadIdx.x;
    int base = blockIdx.x * 64;

    for (int i = t; i < 4096; i += 256) ((float4*)Ws)[i] = ((const float4*)W)[i];
    for (int i = t; i < 2048; i += 256) {
        int node = base + (i >> 5);
        ((float4*)xs)[i] = (node < NN) ? ((const float4*)x)[node * 32 + (i & 31)]
                                       : make_float4(0.f, 0.f, 0.f, 0.f);
    }
    __syncthreads();

    int cx = t & 31;
    int ng = t >> 5;
    float acc[8][4];
#pragma unroll
    for (int j = 0; j < 8; j++) { acc[j][0]=acc[j][1]=acc[j][2]=acc[j][3]=0.f; }

    for (int k = 0; k < 128; k++) {
        float4 w4 = ((float4*)Ws)[k * 32 + cx];
#pragma unroll
        for (int j = 0; j < 8; j++) {
            float xv = xs[(ng * 8 + j) * 128 + k];
            acc[j][0] += xv * w4.x; acc[j][1] += xv * w4.y;
            acc[j][2] += xv * w4.z; acc[j][3] += xv * w4.w;
        }
    }

    int c0 = 4 * cx;
    float as0 = asv[c0], as1 = asv[c0+1], as2 = asv[c0+2], as3 = asv[c0+3];
    float ad0 = adv[c0], ad1 = adv[c0+1], ad2 = adv[c0+2], ad3 = adv[c0+3];
    int head = cx >> 3;

#pragma unroll
    for (int j = 0; j < 8; j++) {
        int node = base + ng * 8 + j;
        bool valid = node < NN;
        float4 o = make_float4(acc[j][0], acc[j][1], acc[j][2], acc[j][3]);
        if (valid) *(float4*)&g_h1[node * 128 + c0] = o;
        float sv = o.x*as0 + o.y*as1 + o.z*as2 + o.w*as3;
        float dv = o.x*ad0 + o.y*ad1 + o.z*ad2 + o.w*ad3;
#pragma unroll
        for (int off = 4; off; off >>= 1) {
            sv += __shfl_down_sync(0xffffffffu, sv, off, 8);
            dv += __shfl_down_sync(0xffffffffu, dv, off, 8);
        }
        if (valid && (cx & 7) == 0) {
            g_as1[node * 4 + head] = sv;
            g_ad1[node * 4 + head] = dv;
        }
    }
}

// ---------------- layer1 aggregation: one pass, light prefetch ---------------
__global__ void k_agg1(const float* __restrict__ bias) {
    int gt = blockIdx.x * blockDim.x + threadIdx.x;
    int d = gt >> 5, lane = gt & 31;
    if (d >= NN) return;
    int e0 = g_rowptr[d], e1 = g_rowptr[d + 1];
    int head = lane >> 3;
    float adh = g_ad1[d * 4 + head];

    float den = 0.f;
    float a0 = 0.f, a1 = 0.f, a2 = 0.f, a3 = 0.f;
    int s_next = (e0 < e1) ? g_csrc[e0] : 0;
    for (int k = e0; k < e1; k++) {
        int s = s_next;                              // warp-uniform
        if (k + 1 < e1) s_next = g_csrc[k + 1];      // prefetch next src
        float ex = __expf(lrelu(g_as1[s * 4 + head] + adh));
        den += ex;
        float4 h = *(const float4*)&g_h1[s * 128 + 4 * lane];
        a0 += ex * h.x; a1 += ex * h.y;
        a2 += ex * h.z; a3 += ex * h.w;
    }
    float inv = 1.f / den;
    int c0 = 4 * lane;
    float4 o;
    o.x = eluf(a0 * inv + bias[c0 + 0]);
    o.y = eluf(a1 * inv + bias[c0 + 1]);
    o.z = eluf(a2 * inv + bias[c0 + 2]);
    o.w = eluf(a3 * inv + bias[c0 + 3]);
    *(float4*)&g_out1[d * 128 + c0] = o;
}

// ---------------- layer2 linear + attention scalars -------------------------
__global__ void k_lin2(const float* __restrict__ W,
                       const float* __restrict__ asv, const float* __restrict__ adv) {
    extern __shared__ float sm[];
    float* Ws = sm;              // 128*32
    float* xs = sm + 128 * 32;   // 128*128
    int t = threadIdx.x;
    int base = blockIdx.x * 128;

    for (int i = t; i < 1024; i += 256) ((float4*)Ws)[i] = ((const float4*)W)[i];
    for (int i = t; i < 4096; i += 256) {
        int node = base + (i >> 5);
        ((float4*)xs)[i] = (node < NN) ? ((const float4*)g_out1)[node * 32 + (i & 31)]
                                       : make_float4(0.f, 0.f, 0.f, 0.f);
    }
    __syncthreads();

    int cx = t & 7;
    int ng = t >> 3;
    float acc[4][4];
#pragma unroll
    for (int j = 0; j < 4; j++) { acc[j][0]=acc[j][1]=acc[j][2]=acc[j][3]=0.f; }

    for (int k = 0; k < 128; k++) {
        float4 w4 = ((float4*)Ws)[k * 8 + cx];
#pragma unroll
        for (int j = 0; j < 4; j++) {
            float xv = xs[(ng * 4 + j) * 128 + k];
            acc[j][0] += xv * w4.x; acc[j][1] += xv * w4.y;
            acc[j][2] += xv * w4.z; acc[j][3] += xv * w4.w;
        }
    }

    int c0 = 4 * cx;
    float as0 = asv[c0], as1 = asv[c0+1], as2 = asv[c0+2], as3 = asv[c0+3];
    float ad0 = adv[c0], ad1 = adv[c0+1], ad2 = adv[c0+2], ad3 = adv[c0+3];

#pragma unroll
    for (int j = 0; j < 4; j++) {
        int node = base + ng * 4 + j;
        bool valid = node < NN;
        float4 o = make_float4(acc[j][0], acc[j][1], acc[j][2], acc[j][3]);
        if (valid) *(float4*)&g_h2[node * 32 + c0] = o;
        float sv = o.x*as0 + o.y*as1 + o.z*as2 + o.w*as3;
        float dv = o.x*ad0 + o.y*ad1 + o.z*ad2 + o.w*ad3;
#pragma unroll
        for (int off = 4; off; off >>= 1) {
            sv += __shfl_down_sync(0xffffffffu, sv, off, 8);
            dv += __shfl_down_sync(0xffffffffu, dv, off, 8);
        }
        if (valid && cx == 0) { g_as2[node] = sv; g_ad2[node] = dv; }
    }
}

// ---------------- layer2 aggregation: one pass + bias/ELU/mean-pool ----------
__global__ void k_agg2(const float* __restrict__ bias, const int* __restrict__ batch) {
    int gt = blockIdx.x * blockDim.x + threadIdx.x;
    int d = gt >> 5, lane = gt & 31;
    if (d >= NN) return;
    int e0 = g_rowptr[d], e1 = g_rowptr[d + 1];
    float ad = g_ad2[d];

    float den = 0.f, acc = 0.f;
    int s_next = (e0 < e1) ? g_csrc[e0] : 0;
    for (int k = e0; k < e1; k++) {
        int s = s_next;
        if (k + 1 < e1) s_next = g_csrc[k + 1];
        float ex = __expf(lrelu(g_as2[s] + ad));
        den += ex;
        acc += ex * g_h2[s * 32 + lane];
    }
    float v = eluf(acc / den + bias[lane]);
    int g = clampi(batch[d], GG - 1);
    atomicAdd(&g_pool[g * 32 + lane], v);
    if (lane == 0) atomicAdd(&g_cnt[g], 1.f);
}

// ---------------- classifier --------------------------------------------------
__global__ void k_cls(const float* __restrict__ Wc1, const float* __restrict__ bc1,
                      const float* __restrict__ Wc2, const float* __restrict__ bc2,
                      float* __restrict__ out) {
    int g = blockIdx.x * blockDim.x + threadIdx.x;
    if (g >= GG) return;
    float inv = 1.f / g_cnt[g];
    float p[32];
#pragma unroll
    for (int c = 0; c < 32; c++) p[c] = g_pool[g * 32 + c] * inv;
    float o = bc2[0];
#pragma unroll
    for (int j = 0; j < 16; j++) {
        float z = bc1[j];
#pragma unroll
        for (int c = 0; c < 32; c++) z += p[c] * Wc1[c * 16 + j];
        z = fmaxf(z, 0.f);
        o += z * Wc2[j];
    }
    out[g] = o;
}

// ---------------- launch ------------------------------------------------------
// Fork-join: CSR build (init/deg/bsum/chscan/scatter) on side stream, k_lin1 on
// the capture stream, join before k_agg1. Handles are created once (host-side
// only); the captured work is identical on every call.
extern "C" void kernel_launch(void* const* d_in, const int* in_sizes, int n_in,
                              void* d_out, int out_size) {
    const float* x     = (const float*)d_in[0];
    const int*   ei    = (const int*)d_in[1];     // int64 -> int32 on device
    const int*   batch = (const int*)d_in[3];     // int64 -> int32
    const float* W1  = (const float*)d_in[4];
    const float* as1 = (const float*)d_in[5];
    const float* ad1 = (const float*)d_in[6];
    const float* b1  = (const float*)d_in[7];
    const float* W2  = (const float*)d_in[8];
    const float* as2 = (const float*)d_in[9];
    const float* ad2 = (const float*)d_in[10];
    const float* b2  = (const float*)d_in[11];
    const float* Wc1 = (const float*)d_in[12];
    const float* bc1 = (const float*)d_in[13];
    const float* Wc2 = (const float*)d_in[14];
    const float* bc2 = (const float*)d_in[15];
    float* out = (float*)d_out;

    static cudaStream_t s2 = nullptr;
    static cudaEvent_t ev_fork = nullptr, ev_join = nullptr;
    if (s2 == nullptr) {
        cudaStreamCreateWithFlags(&s2, cudaStreamNonBlocking);
        cudaEventCreateWithFlags(&ev_fork, cudaEventDisableTiming);
        cudaEventCreateWithFlags(&ev_join, cudaEventDisableTiming);
    }

    cudaFuncSetAttribute(k_lin1, cudaFuncAttributeMaxDynamicSharedMemorySize, 98304);
    cudaFuncSetAttribute(k_lin2, cudaFuncAttributeMaxDynamicSharedMemorySize, 81920);

    // fork: side stream does CSR build
    cudaEventRecord(ev_fork, 0);
    cudaStreamWaitEvent(s2, ev_fork, 0);
    k_init<<<256, 256, 0, s2>>>();
    k_deg<<<(ET / 4 + 255) / 256, 256, 0, s2>>>(ei);
    k_bsum<<<NCHUNK, 256, 0, s2>>>();
    k_chscan<<<NCHUNK, 256, 0, s2>>>();
    k_scatter<<<(ET / 4 + 255) / 256, 256, 0, s2>>>(ei);
    cudaEventRecord(ev_join, s2);

    // main stream: linear1 concurrently
    k_lin1<<<(NN + 63) / 64, 256, 98304>>>(x, W1, as1, ad1);

    // join, then dependent chain
    cudaStreamWaitEvent(0, ev_join, 0);
    k_agg1<<<(NN * 32 + 255) / 256, 256>>>(b1);
    k_lin2<<<(NN + 127) / 128, 256, 81920>>>(W2, as2, ad2);
    k_agg2<<<(NN * 32 + 255) / 256, 256>>>(b2, batch);
    k_cls<<<2, 256>>>(Wc1, bc1, Wc2, bc2, out);
}